// round 5
// baseline (speedup 1.0000x reference)
#include <cuda_runtime.h>
#include <math.h>

// Problem constants (fixed by setup_inputs: B=4, N=2048, D_MODEL=512)
#define N_PTS   2048
#define N_WAVES 256              // D_MODEL / 2
#define T       16               // tile rows
#define NT      (N_PTS / T)      // 128 tiles
#define W       8                // j-tiles per strip
#define NSTRIPS (NT / W)         // 16
#define F_MUFU  12               // ii < F_MUFU -> MUFU path, rest -> FMA poly path

typedef unsigned long long ull;

__device__ __forceinline__ void red_add_v2(float* p, float x, float y) {
    asm volatile("red.global.add.v2.f32 [%0], {%1, %2};"
                 :: "l"(p), "f"(x), "f"(y) : "memory");
}

__device__ __forceinline__ ull pack2(float lo, float hi) {
    ull v; asm("mov.b64 %0, {%1, %2};" : "=l"(v) : "f"(lo), "f"(hi)); return v;
}
__device__ __forceinline__ void unpack2(ull v, float& lo, float& hi) {
    asm("mov.b64 {%0, %1}, %2;" : "=f"(lo), "=f"(hi) : "l"(v));
}
// packed dual-FMA on the FMA pipe: d.lo = a.lo*b.lo+c.lo, d.hi = a.hi*b.hi+c.hi
__device__ __forceinline__ ull fma2(ull a, ull b, ull c) {
    ull d; asm("fma.rn.f32x2 %0, %1, %2, %3;" : "=l"(d) : "l"(a), "l"(b), "l"(c));
    return d;
}

__global__ __launch_bounds__(256, 2) void spatial_embedding_sym_kernel(
    const float* __restrict__ coords,          // (B, N, 3)
    const unsigned char* __restrict__ mask,    // (B, N) bool, 1 = padded
    float* __restrict__ out)                   // (B, N, 512), pre-zeroed
{
    __shared__ float2 sh_ra[T * T];            // (r, ampA)
    __shared__ ull    sh_b2[T * T];            // (ampB, ampB) pre-splatted
    __shared__ float sxi[T], syi[T], szi[T], svi[T];
    __shared__ float sxj[T], syj[T], szj[T], svj[T];

    const int strip = blockIdx.x;
    const int ti    = blockIdx.y;
    const int b     = blockIdx.z;
    const int tid   = threadIdx.x;             // wave index m

    const int tj_end = strip * W + W;
    if (tj_end <= ti) return;                  // strip entirely below diagonal
    const int tj_beg = (ti > strip * W) ? ti : strip * W;

    const float* cb = coords + (size_t)b * N_PTS * 3;
    const unsigned char* mb = mask + (size_t)b * N_PTS;

    // k_m = 2*pi / lam_m, lam = geomspace(2, 100, 256); double to match numpy
    const double tt = (double)tid / (double)(N_WAVES - 1);
    const float  k  = (float)(6.283185307179586 / (2.0 * pow(50.0, tt)));

    // packed poly coefficients: (sin-coef, cos-coef) pairs
    const ull C0 = pack2(-1.9841270e-4f,  2.4801587e-5f);
    const ull C1 = pack2( 8.3333310e-3f, -1.3888889e-3f);
    const ull C2 = pack2(-1.6666667e-1f,  4.1666668e-2f);
    const ull C3 = pack2( 1.0f,          -0.5f);
    const ull C4 = pack2( 0.0f,           1.0f);

    if (tid < T) {
        const int ig = ti * T + tid;
        sxi[tid] = cb[ig * 3 + 0];
        syi[tid] = cb[ig * 3 + 1];
        szi[tid] = cb[ig * 3 + 2];
        svi[tid] = (mb[ig] == 0) ? 1.0f : 0.0f;
    }

    // i-side packed accumulators (re, im) persist across the whole strip
    ull aiP[T];
    #pragma unroll
    for (int q = 0; q < T; ++q) aiP[q] = 0ull;

    for (int tj = tj_beg; tj < tj_end; ++tj) {
        __syncthreads();   // covers svi/sxi visibility and shared reuse
        if (tid < T) {
            const int jg = tj * T + tid;
            sxj[tid] = cb[jg * 3 + 0];
            syj[tid] = cb[jg * 3 + 1];
            szj[tid] = cb[jg * 3 + 2];
            svj[tid] = (mb[jg] == 0) ? 1.0f : 0.0f;
        }
        __syncthreads();

        // ---- Phase A: 256 threads build the 16x16 pair table ----
        {
            const int ii = tid >> 4;
            const int jj = tid & (T - 1);
            const float dx = sxi[ii] - sxj[jj];
            const float dy = syi[ii] - syj[jj];
            const float dz = szi[ii] - szj[jj];
            float sq = fmaf(dx, dx, fmaf(dy, dy, dz * dz));
            const bool self = (ti == tj) && (ii == jj);
            if (self) sq = 1.0f;                      // sq_safe
            const float rs = rsqrtf(sq);
            const float r  = sq * rs;
            const float ar = 0.07957747154594767f * rs;   // 1/(4*pi*r)
            const float ampA = (!self && svj[jj] != 0.0f) ? ar : 0.0f;
            const float ampB = (ti != tj && svi[ii] != 0.0f) ? ar : 0.0f;
            sh_ra[tid] = make_float2(r, ampA);
            sh_b2[tid] = pack2(ampB, ampB);
        }
        __syncthreads();

        // ---- Phase B: each thread (wave m) sweeps 256 pairs ----
        ull ajP[T];
        #pragma unroll
        for (int q = 0; q < T; ++q) ajP[q] = 0ull;

        // MUFU path: ii in [0, F_MUFU)
        #pragma unroll
        for (int ii = 0; ii < F_MUFU; ++ii) {
            #pragma unroll
            for (int jj = 0; jj < T; ++jj) {
                const float2 ra = sh_ra[ii * T + jj];
                const ull    b2 = sh_b2[ii * T + jj];
                const float ph = k * ra.x;
                const float s = __sinf(ph);
                const float c = __cosf(ph);
                const ull cs = pack2(c, s);
                const ull a2 = pack2(ra.y, ra.y);
                aiP[ii] = fma2(cs, a2, aiP[ii]);
                ajP[jj] = fma2(cs, b2, ajP[jj]);
            }
        }
        // FMA-poly path: ii in [F_MUFU, T) — packed sin/cos polynomial
        #pragma unroll
        for (int ii = F_MUFU; ii < T; ++ii) {
            #pragma unroll
            for (int jj = 0; jj < T; ++jj) {
                const float2 ra = sh_ra[ii * T + jj];
                const ull    b2 = sh_b2[ii * T + jj];
                const float ph = k * ra.x;
                // range reduction: qf = rint(ph * 2/pi), x in [-pi/4, pi/4]
                const float q  = fmaf(ph, 0.63661977236758134f, 12582912.0f);
                const float qf = q - 12582912.0f;
                float x = fmaf(qf, -1.57079637050628662f, ph);
                x = fmaf(qf, 4.37113900018624283e-8f, x);
                const float x2 = x * x;
                // packed (sin, cos) polynomials
                const ull xx = pack2(x2, x2);
                ull p = fma2(xx, C0, C1);
                p = fma2(xx, p, C2);
                p = fma2(xx, p, C3);               // (1 + x2*Ps, -0.5 + x2*Pc)
                const ull r2 = fma2(pack2(x, x2), p, C4); // (sin_r, cos_r)
                float s0, c0;
                unpack2(r2, s0, c0);
                // quadrant fixup on ALU pipe
                const unsigned qb = __float_as_uint(q);
                const bool swap = (qb & 1u);
                const float s1 = swap ? c0 : s0;
                const float c1 = swap ? s0 : c0;
                const float s = __uint_as_float(__float_as_uint(s1) ^ ((qb & 2u) << 30));
                const float c = __uint_as_float(__float_as_uint(c1) ^ (((qb + 1u) & 2u) << 30));
                const ull cs = pack2(c, s);
                const ull a2 = pack2(ra.y, ra.y);
                aiP[ii] = fma2(cs, a2, aiP[ii]);
                ajP[jj] = fma2(cs, b2, ajP[jj]);
            }
        }

        // flush j-side partials (skip diagonal tile: ampB was 0 there)
        if (tj != ti) {
            #pragma unroll
            for (int jj = 0; jj < T; ++jj) {
                const float v = svj[jj];              // target-row validity
                float re, im;
                unpack2(ajP[jj], re, im);
                float* p = out + ((size_t)(b * N_PTS) + tj * T + jj) * (2 * N_WAVES)
                               + 2 * tid;
                red_add_v2(p, re * v, im * v);
            }
        }
    }

    // flush i-side partials once per block
    #pragma unroll
    for (int ii = 0; ii < T; ++ii) {
        const float v = svi[ii];                      // target-row validity
        float re, im;
        unpack2(aiP[ii], re, im);
        float* p = out + ((size_t)(b * N_PTS) + ti * T + ii) * (2 * N_WAVES)
                       + 2 * tid;
        red_add_v2(p, re * v, im * v);
    }
}

extern "C" void kernel_launch(void* const* d_in, const int* in_sizes, int n_in,
                              void* d_out, int out_size)
{
    const float* coords       = (const float*)d_in[0];
    const unsigned char* mask = (const unsigned char*)d_in[1];
    float* out                = (float*)d_out;

    const int BN = in_sizes[1];        // B * N
    const int B  = BN / N_PTS;

    // output is accumulated atomically -> must start from zero
    cudaMemsetAsync(d_out, 0, (size_t)out_size * sizeof(float), 0);

    dim3 grid(NSTRIPS, NT, B);
    spatial_embedding_sym_kernel<<<grid, 256>>>(coords, mask, out);
}

// round 6
// speedup vs baseline: 1.0297x; 1.0297x over previous
#include <cuda_runtime.h>
#include <math.h>

// Problem constants (fixed by setup_inputs: B=4, N=2048, D_MODEL=512)
#define N_PTS   2048
#define N_WAVES 256              // D_MODEL / 2
#define T       16               // tile rows
#define HJ      8                // jj-half width (j accumulators live per half)
#define NT      (N_PTS / T)      // 128 tiles
#define W       8                // j-tiles per strip
#define NSTRIPS (NT / W)         // 16
#define F_MUFU  12               // ii < F_MUFU -> MUFU path, rest -> FMA poly path

typedef unsigned long long ull;

__device__ __forceinline__ void red_add_v2(float* p, float x, float y) {
    asm volatile("red.global.add.v2.f32 [%0], {%1, %2};"
                 :: "l"(p), "f"(x), "f"(y) : "memory");
}
__device__ __forceinline__ ull pack2(float lo, float hi) {
    ull v; asm("mov.b64 %0, {%1, %2};" : "=l"(v) : "f"(lo), "f"(hi)); return v;
}
__device__ __forceinline__ void unpack2(ull v, float& lo, float& hi) {
    asm("mov.b64 {%0, %1}, %2;" : "=f"(lo), "=f"(hi) : "l"(v));
}
// packed dual-FMA on the FMA pipe
__device__ __forceinline__ ull fma2(ull a, ull b, ull c) {
    ull d; asm("fma.rn.f32x2 %0, %1, %2, %3;" : "=l"(d) : "l"(a), "l"(b), "l"(c));
    return d;
}

__global__ __launch_bounds__(256, 3) void spatial_embedding_sym_kernel(
    const float* __restrict__ coords,          // (B, N, 3)
    const unsigned char* __restrict__ mask,    // (B, N) bool, 1 = padded
    float* __restrict__ out)                   // (B, N, 512), pre-zeroed
{
    __shared__ float2 sh_ra[T * T];            // (r, ampA)
    __shared__ ull    sh_b2[T * T];            // (ampB, ampB) pre-splatted
    __shared__ float sxi[T], syi[T], szi[T], svi[T];
    __shared__ float sxj[T], syj[T], szj[T], svj[T];

    const int strip = blockIdx.x;
    const int ti    = blockIdx.y;
    const int b     = blockIdx.z;
    const int tid   = threadIdx.x;             // wave index m

    const int tj_end = strip * W + W;
    if (tj_end <= ti) return;                  // strip entirely below diagonal
    const int tj_beg = (ti > strip * W) ? ti : strip * W;

    const float* cb = coords + (size_t)b * N_PTS * 3;
    const unsigned char* mb = mask + (size_t)b * N_PTS;

    // k_m = 2*pi / lam_m, lam = geomspace(2, 100, 256); double to match numpy
    const double tt = (double)tid / (double)(N_WAVES - 1);
    const float  k  = (float)(6.283185307179586 / (2.0 * pow(50.0, tt)));

    // packed poly coefficients: (sin-coef, cos-coef) pairs
    const ull C0 = pack2(-1.9841270e-4f,  2.4801587e-5f);
    const ull C1 = pack2( 8.3333310e-3f, -1.3888889e-3f);
    const ull C2 = pack2(-1.6666667e-1f,  4.1666668e-2f);
    const ull C3 = pack2( 1.0f,          -0.5f);
    const ull C4 = pack2( 0.0f,           1.0f);

    if (tid < T) {
        const int ig = ti * T + tid;
        sxi[tid] = cb[ig * 3 + 0];
        syi[tid] = cb[ig * 3 + 1];
        szi[tid] = cb[ig * 3 + 2];
        svi[tid] = (mb[ig] == 0) ? 1.0f : 0.0f;
    }

    // i-side scalar accumulators persist across the whole strip (32 regs)
    float aiR[T], aiI[T];
    #pragma unroll
    for (int q = 0; q < T; ++q) { aiR[q] = 0.0f; aiI[q] = 0.0f; }

    for (int tj = tj_beg; tj < tj_end; ++tj) {
        __syncthreads();   // prev Phase B done before shared overwrite
        if (tid < T) {
            const int jg = tj * T + tid;
            sxj[tid] = cb[jg * 3 + 0];
            syj[tid] = cb[jg * 3 + 1];
            szj[tid] = cb[jg * 3 + 2];
            svj[tid] = (mb[jg] == 0) ? 1.0f : 0.0f;
        }
        __syncthreads();

        // ---- Phase A: 256 threads build the 16x16 pair table ----
        {
            const int ii = tid >> 4;
            const int jj = tid & (T - 1);
            const float dx = sxi[ii] - sxj[jj];
            const float dy = syi[ii] - syj[jj];
            const float dz = szi[ii] - szj[jj];
            float sq = fmaf(dx, dx, fmaf(dy, dy, dz * dz));
            const bool self = (ti == tj) && (ii == jj);
            if (self) sq = 1.0f;                      // sq_safe
            const float rs = rsqrtf(sq);
            const float r  = sq * rs;
            const float ar = 0.07957747154594767f * rs;   // 1/(4*pi*r)
            const float ampA = (!self && svj[jj] != 0.0f) ? ar : 0.0f;
            const float ampB = (ti != tj && svi[ii] != 0.0f) ? ar : 0.0f;
            sh_ra[tid] = make_float2(r, ampA);
            sh_b2[tid] = pack2(ampB, ampB);
        }
        __syncthreads();

        // ---- Phase B: two jj-half passes; each keeps only 8 j-accumulators
        #pragma unroll
        for (int h = 0; h < 2; ++h) {
            ull ajP[HJ];
            #pragma unroll
            for (int q = 0; q < HJ; ++q) ajP[q] = 0ull;

            // MUFU path: ii in [0, F_MUFU)
            #pragma unroll
            for (int ii = 0; ii < F_MUFU; ++ii) {
                #pragma unroll
                for (int jj = 0; jj < HJ; ++jj) {
                    const int g = ii * T + h * HJ + jj;
                    const float2 ra = sh_ra[g];
                    const ull    b2 = sh_b2[g];
                    const float ph = k * ra.x;
                    const float s = __sinf(ph);
                    const float c = __cosf(ph);
                    aiR[ii] = fmaf(ra.y, c, aiR[ii]);
                    aiI[ii] = fmaf(ra.y, s, aiI[ii]);
                    ajP[jj] = fma2(pack2(c, s), b2, ajP[jj]);
                }
            }
            // FMA-poly path: ii in [F_MUFU, T)
            #pragma unroll
            for (int ii = F_MUFU; ii < T; ++ii) {
                #pragma unroll
                for (int jj = 0; jj < HJ; ++jj) {
                    const int g = ii * T + h * HJ + jj;
                    const float2 ra = sh_ra[g];
                    const ull    b2 = sh_b2[g];
                    const float ph = k * ra.x;
                    // range reduction: qf = rint(ph*2/pi), x in [-pi/4, pi/4]
                    const float q  = fmaf(ph, 0.63661977236758134f, 12582912.0f);
                    const float qf = q - 12582912.0f;
                    float x = fmaf(qf, -1.57079637050628662f, ph);
                    x = fmaf(qf, 4.37113900018624283e-8f, x);
                    const float x2 = x * x;
                    const ull xx = pack2(x2, x2);
                    ull p = fma2(xx, C0, C1);
                    p = fma2(xx, p, C2);
                    p = fma2(xx, p, C3);
                    const ull r2 = fma2(pack2(x, x2), p, C4); // (sin_r, cos_r)
                    float s0, c0;
                    unpack2(r2, s0, c0);
                    const unsigned qb = __float_as_uint(q);
                    const bool swap = (qb & 1u);
                    const float s1 = swap ? c0 : s0;
                    const float c1 = swap ? s0 : c0;
                    const float s = __uint_as_float(__float_as_uint(s1) ^ ((qb & 2u) << 30));
                    const float c = __uint_as_float(__float_as_uint(c1) ^ (((qb + 1u) & 2u) << 30));
                    aiR[ii] = fmaf(ra.y, c, aiR[ii]);
                    aiI[ii] = fmaf(ra.y, s, aiI[ii]);
                    ajP[jj] = fma2(pack2(c, s), b2, ajP[jj]);
                }
            }

            // flush this jj-half (skip diagonal tile: ampB was 0 there)
            if (tj != ti) {
                #pragma unroll
                for (int jj = 0; jj < HJ; ++jj) {
                    const int jglob = h * HJ + jj;
                    const float v = svj[jglob];        // target-row validity
                    float re, im;
                    unpack2(ajP[jj], re, im);
                    float* p = out + ((size_t)(b * N_PTS) + tj * T + jglob) * (2 * N_WAVES)
                                   + 2 * tid;
                    red_add_v2(p, re * v, im * v);
                }
            }
        }
    }

    // flush i-side partials once per block
    #pragma unroll
    for (int ii = 0; ii < T; ++ii) {
        const float v = svi[ii];                      // target-row validity
        float* p = out + ((size_t)(b * N_PTS) + ti * T + ii) * (2 * N_WAVES)
                       + 2 * tid;
        red_add_v2(p, aiR[ii] * v, aiI[ii] * v);
    }
}

extern "C" void kernel_launch(void* const* d_in, const int* in_sizes, int n_in,
                              void* d_out, int out_size)
{
    const float* coords       = (const float*)d_in[0];
    const unsigned char* mask = (const unsigned char*)d_in[1];
    float* out                = (float*)d_out;

    const int BN = in_sizes[1];        // B * N
    const int B  = BN / N_PTS;

    // output is accumulated atomically -> must start from zero
    cudaMemsetAsync(d_out, 0, (size_t)out_size * sizeof(float), 0);

    dim3 grid(NSTRIPS, NT, B);
    spatial_embedding_sym_kernel<<<grid, 256>>>(coords, mask, out);
}

// round 7
// speedup vs baseline: 1.1377x; 1.1049x over previous
#include <cuda_runtime.h>
#include <math.h>

// Problem constants (fixed by setup_inputs: B=4, N=2048, D_MODEL=512)
#define N_PTS   2048
#define N_WAVES 256              // D_MODEL / 2
#define T       16               // tile rows
#define HJ      8                // jj-half width (j accumulators live per half)
#define NT      (N_PTS / T)      // 128 tiles
#define W       8                // j-tiles per strip
#define NSTRIPS (NT / W)         // 16
#define F_MUFU  13               // ii < F_MUFU -> MUFU path, rest -> FMA poly path

typedef unsigned long long ull;

__device__ __forceinline__ void red_add_v2(float* p, float x, float y) {
    asm volatile("red.global.add.v2.f32 [%0], {%1, %2};"
                 :: "l"(p), "f"(x), "f"(y) : "memory");
}
__device__ __forceinline__ ull pack2(float lo, float hi) {
    ull v; asm("mov.b64 %0, {%1, %2};" : "=l"(v) : "f"(lo), "f"(hi)); return v;
}
__device__ __forceinline__ void unpack2(ull v, float& lo, float& hi) {
    asm("mov.b64 {%0, %1}, %2;" : "=f"(lo), "=f"(hi) : "l"(v));
}
__device__ __forceinline__ ull fma2(ull a, ull b, ull c) {
    ull d; asm("fma.rn.f32x2 %0, %1, %2, %3;" : "=l"(d) : "l"(a), "l"(b), "l"(c));
    return d;
}
__device__ __forceinline__ ull mul2(ull a, ull b) {
    ull d; asm("mul.rn.f32x2 %0, %1, %2;" : "=l"(d) : "l"(a), "l"(b));
    return d;
}

__global__ __launch_bounds__(256, 3) void spatial_embedding_sym_kernel(
    const float* __restrict__ coords,          // (B, N, 3)
    const unsigned char* __restrict__ mask,    // (B, N) bool, 1 = padded
    float* __restrict__ out)                   // (B, N, 512), pre-zeroed
{
    __shared__ float4 sh4[T * T];              // (r, ampA, ampB, ampB)
    __shared__ float sxi[T], syi[T], szi[T], svi[T];
    __shared__ float sxj[T], syj[T], szj[T], svj[T];

    const int strip = blockIdx.x;
    const int ti    = blockIdx.y;
    const int b     = blockIdx.z;
    const int tid   = threadIdx.x;             // wave index m

    const int tj_end = strip * W + W;
    if (tj_end <= ti) return;                  // strip entirely below diagonal
    const int tj_beg = (ti > strip * W) ? ti : strip * W;

    const float* cb = coords + (size_t)b * N_PTS * 3;
    const unsigned char* mb = mask + (size_t)b * N_PTS;

    // k_m = 2*pi / lam_m, lam = geomspace(2, 100, 256); double to match numpy
    const double tt = (double)tid / (double)(N_WAVES - 1);
    const float  k  = (float)(6.283185307179586 / (2.0 * pow(50.0, tt)));

    // packed Taylor coefficients: (cos_n, sin_n) for powers of x^2
    const ull P0 = pack2( 1.0f,            1.0f);
    const ull P1 = pack2(-0.5f,           -1.66666672e-1f);
    const ull P2 = pack2( 4.16666679e-2f,  8.33333358e-3f);
    const ull P3 = pack2(-1.38888893e-3f, -1.98412701e-4f);
    const ull P4 = pack2( 2.48015876e-5f,  2.75573192e-6f);
    const ull P5 = pack2(-2.75573192e-7f, -2.50521084e-8f);
    const ull P6 = pack2( 2.08767570e-9f,  1.60590438e-10f);

    if (tid < T) {
        const int ig = ti * T + tid;
        sxi[tid] = cb[ig * 3 + 0];
        syi[tid] = cb[ig * 3 + 1];
        szi[tid] = cb[ig * 3 + 2];
        svi[tid] = (mb[ig] == 0) ? 1.0f : 0.0f;
    }

    // i-side scalar accumulators persist across the whole strip (32 regs)
    float aiR[T], aiI[T];
    #pragma unroll
    for (int q = 0; q < T; ++q) { aiR[q] = 0.0f; aiI[q] = 0.0f; }

    for (int tj = tj_beg; tj < tj_end; ++tj) {
        __syncthreads();   // prev Phase B done before shared overwrite
        if (tid < T) {
            const int jg = tj * T + tid;
            sxj[tid] = cb[jg * 3 + 0];
            syj[tid] = cb[jg * 3 + 1];
            szj[tid] = cb[jg * 3 + 2];
            svj[tid] = (mb[jg] == 0) ? 1.0f : 0.0f;
        }
        __syncthreads();

        // ---- Phase A: 256 threads build the 16x16 pair table ----
        {
            const int ii = tid >> 4;
            const int jj = tid & (T - 1);
            const float dx = sxi[ii] - sxj[jj];
            const float dy = syi[ii] - syj[jj];
            const float dz = szi[ii] - szj[jj];
            float sq = fmaf(dx, dx, fmaf(dy, dy, dz * dz));
            const bool self = (ti == tj) && (ii == jj);
            if (self) sq = 1.0f;                      // sq_safe
            const float rs = rsqrtf(sq);
            const float r  = sq * rs;
            const float ar = 0.07957747154594767f * rs;   // 1/(4*pi*r)
            const float ampA = (!self && svj[jj] != 0.0f) ? ar : 0.0f;
            const float ampB = (ti != tj && svi[ii] != 0.0f) ? ar : 0.0f;
            sh4[tid] = make_float4(r, ampA, ampB, ampB);
        }
        __syncthreads();

        // ---- Phase B: two jj-half passes, pipes interleaved per item ----
        #pragma unroll 1
        for (int h = 0; h < 2; ++h) {
            ull ajP[HJ];                      // packed (re, im) j-side accum
            #pragma unroll
            for (int q = 0; q < HJ; ++q) ajP[q] = 0ull;

            #pragma unroll
            for (int jj = 0; jj < HJ; ++jj) {
                #pragma unroll
                for (int ii = 0; ii < T; ++ii) {
                    const float4 ra = sh4[ii * T + h * HJ + jj];  // LDS.128
                    const ull b2 = pack2(ra.z, ra.w);             // reg pair, free
                    const float ph = k * ra.x;
                    float s, c;
                    if (ii < F_MUFU) {
                        // MUFU path
                        s = __sinf(ph);
                        c = __cosf(ph);
                    } else {
                        // FMA-pipe path: reduce to [-pi, pi], packed Taylor
                        const float q  = fmaf(ph, 0.15915494309189535f, 12582912.0f);
                        const float nf = q - 12582912.0f;
                        float x = fmaf(nf, -6.2831855f, ph);      // -2pi_hi
                        x = fmaf(nf, 1.7484555e-7f, x);           // -2pi_lo
                        const ull xs = pack2(x, x);
                        const ull xx = mul2(xs, xs);              // (x2, x2)
                        ull p = fma2(xx, P6, P5);
                        p = fma2(xx, p, P4);
                        p = fma2(xx, p, P3);
                        p = fma2(xx, p, P2);
                        p = fma2(xx, p, P1);
                        p = fma2(xx, p, P0);                      // (cos, sin/x)
                        float plo, phi;
                        unpack2(p, plo, phi);                     // free (reg halves)
                        c = plo;
                        s = x * phi;
                    }
                    aiR[ii] = fmaf(ra.y, c, aiR[ii]);
                    aiI[ii] = fmaf(ra.y, s, aiI[ii]);
                    ajP[jj] = fma2(pack2(c, s), b2, ajP[jj]);
                }
            }

            // flush this jj-half (skip diagonal tile: ampB was 0 there)
            if (tj != ti) {
                #pragma unroll
                for (int jj = 0; jj < HJ; ++jj) {
                    const int jglob = h * HJ + jj;
                    const float v = svj[jglob];        // target-row validity
                    float re, im;
                    unpack2(ajP[jj], re, im);
                    float* p = out + ((size_t)(b * N_PTS) + tj * T + jglob) * (2 * N_WAVES)
                                   + 2 * tid;
                    red_add_v2(p, re * v, im * v);
                }
            }
        }
    }

    // flush i-side partials once per block
    #pragma unroll
    for (int ii = 0; ii < T; ++ii) {
        const float v = svi[ii];                      // target-row validity
        float* p = out + ((size_t)(b * N_PTS) + ti * T + ii) * (2 * N_WAVES)
                       + 2 * tid;
        red_add_v2(p, aiR[ii] * v, aiI[ii] * v);
    }
}

extern "C" void kernel_launch(void* const* d_in, const int* in_sizes, int n_in,
                              void* d_out, int out_size)
{
    const float* coords       = (const float*)d_in[0];
    const unsigned char* mask = (const unsigned char*)d_in[1];
    float* out                = (float*)d_out;

    const int BN = in_sizes[1];        // B * N
    const int B  = BN / N_PTS;

    // output is accumulated atomically -> must start from zero
    cudaMemsetAsync(d_out, 0, (size_t)out_size * sizeof(float), 0);

    dim3 grid(NSTRIPS, NT, B);
    spatial_embedding_sym_kernel<<<grid, 256>>>(coords, mask, out);
}